// round 1
// baseline (speedup 1.0000x reference)
#include <cuda_runtime.h>

#define B_ 16
#define N_ 1024
#define D_ 128

// Scratch (device globals — no allocation allowed)
__device__ float d_h[B_*N_*D_];                 // 8 MB
__device__ float d_g[B_*N_*D_];                 // 8 MB
__device__ float d_T[(size_t)B_*N_*N_];         // 64 MB
__device__ float d_numer[(size_t)B_*N_*N_];     // 64 MB
__device__ float d_csum[B_*N_];
__device__ float d_rsum[B_*N_];
__device__ float d_WwT[D_*D_];

// ---------------------------------------------------------------------------
// Transpose Ww so h = x @ WwT is an NN GEMM (conflict-free smem pattern)
// ---------------------------------------------------------------------------
__global__ void k_transpose(const float* __restrict__ W){
    int idx = blockIdx.x*256 + threadIdx.x;   // 64 blocks * 256 = 16384
    int r = idx >> 7, c = idx & 127;
    d_WwT[c*D_ + r] = W[r*D_ + c];
}

// ---------------------------------------------------------------------------
// Generic NN tile: out[r,c] = sum_k Arows[r,k]*Brows[k,c] (+bias[c])
// Block: 32 rows x 128 cols, 256 threads, 4x4 micro-tile per thread.
// ---------------------------------------------------------------------------
__device__ __forceinline__ void nn_tile(const float* __restrict__ Arows,
                                        const float* __restrict__ Brows,
                                        const float* __restrict__ bias,
                                        float* __restrict__ out){
    __shared__ float sA[32*32];
    __shared__ float sB[32*D_];
    int tid = threadIdx.x;
    int tx = tid & 31, ty = tid >> 5;
    int rowBase = blockIdx.x << 5;
    float acc[4][4] = {};

    for (int k0 = 0; k0 < D_; k0 += 32){
        {
            int r = tid >> 3, c4 = (tid & 7) << 2;
            *(float4*)&sA[r*32 + c4] =
                *(const float4*)&Arows[(size_t)(rowBase + r)*D_ + k0 + c4];
        }
        #pragma unroll
        for (int it = 0; it < 4; ++it){
            int lin = (it << 8) + tid;
            int r = lin >> 5, c4 = (lin & 31) << 2;
            *(float4*)&sB[r*D_ + c4] =
                *(const float4*)&Brows[(size_t)(k0 + r)*D_ + c4];
        }
        __syncthreads();
        #pragma unroll
        for (int kk = 0; kk < 32; ++kk){
            float a0 = sA[(ty*4+0)*32 + kk];
            float a1 = sA[(ty*4+1)*32 + kk];
            float a2 = sA[(ty*4+2)*32 + kk];
            float a3 = sA[(ty*4+3)*32 + kk];
            float4 b = *(float4*)&sB[kk*D_ + (tx<<2)];
            acc[0][0] = fmaf(a0,b.x,acc[0][0]); acc[0][1] = fmaf(a0,b.y,acc[0][1]);
            acc[0][2] = fmaf(a0,b.z,acc[0][2]); acc[0][3] = fmaf(a0,b.w,acc[0][3]);
            acc[1][0] = fmaf(a1,b.x,acc[1][0]); acc[1][1] = fmaf(a1,b.y,acc[1][1]);
            acc[1][2] = fmaf(a1,b.z,acc[1][2]); acc[1][3] = fmaf(a1,b.w,acc[1][3]);
            acc[2][0] = fmaf(a2,b.x,acc[2][0]); acc[2][1] = fmaf(a2,b.y,acc[2][1]);
            acc[2][2] = fmaf(a2,b.z,acc[2][2]); acc[2][3] = fmaf(a2,b.w,acc[2][3]);
            acc[3][0] = fmaf(a3,b.x,acc[3][0]); acc[3][1] = fmaf(a3,b.y,acc[3][1]);
            acc[3][2] = fmaf(a3,b.z,acc[3][2]); acc[3][3] = fmaf(a3,b.w,acc[3][3]);
        }
        __syncthreads();
    }
    float4 bv = make_float4(0.f,0.f,0.f,0.f);
    if (bias) bv = *(const float4*)&bias[tx<<2];
    #pragma unroll
    for (int i = 0; i < 4; ++i){
        float4 o;
        o.x = acc[i][0]+bv.x; o.y = acc[i][1]+bv.y;
        o.z = acc[i][2]+bv.z; o.w = acc[i][3]+bv.w;
        *(float4*)&out[(size_t)(rowBase + ty*4 + i)*D_ + (tx<<2)] = o;
    }
}

__global__ void k_h(const float* __restrict__ x, const float* __restrict__ Wb){
    nn_tile(x, d_WwT, Wb, d_h);
}
__global__ void k_g(const float* __restrict__ A){
    nn_tile(d_h, A, nullptr, d_g);
}

// ---------------------------------------------------------------------------
// T[b,p,q] = g[b,p,:] . h[b,q,:]   (NT GEMM, 64x64 tile, K=128 in chunks of 16)
// ---------------------------------------------------------------------------
__global__ void k_score(){
    __shared__ float sG[16*68];
    __shared__ float sH[16*68];
    int tid = threadIdx.x;
    int tx = tid & 15, ty = tid >> 4;
    int b  = blockIdx.z;
    int p0 = blockIdx.y << 6, q0 = blockIdx.x << 6;
    const float* gp = d_g + (size_t)(b*N_ + p0)*D_;
    const float* hq = d_h + (size_t)(b*N_ + q0)*D_;
    float acc[4][4] = {};

    for (int k0 = 0; k0 < D_; k0 += 16){
        int r = tid >> 2, k4 = (tid & 3) << 2;
        float4 va = *(const float4*)&gp[(size_t)r*D_ + k0 + k4];
        float4 vb = *(const float4*)&hq[(size_t)r*D_ + k0 + k4];
        sG[(k4+0)*68+r]=va.x; sG[(k4+1)*68+r]=va.y;
        sG[(k4+2)*68+r]=va.z; sG[(k4+3)*68+r]=va.w;
        sH[(k4+0)*68+r]=vb.x; sH[(k4+1)*68+r]=vb.y;
        sH[(k4+2)*68+r]=vb.z; sH[(k4+3)*68+r]=vb.w;
        __syncthreads();
        #pragma unroll
        for (int kk = 0; kk < 16; ++kk){
            float4 a  = *(float4*)&sG[kk*68 + (ty<<2)];
            float4 bq = *(float4*)&sH[kk*68 + (tx<<2)];
            acc[0][0]=fmaf(a.x,bq.x,acc[0][0]); acc[0][1]=fmaf(a.x,bq.y,acc[0][1]);
            acc[0][2]=fmaf(a.x,bq.z,acc[0][2]); acc[0][3]=fmaf(a.x,bq.w,acc[0][3]);
            acc[1][0]=fmaf(a.y,bq.x,acc[1][0]); acc[1][1]=fmaf(a.y,bq.y,acc[1][1]);
            acc[1][2]=fmaf(a.y,bq.z,acc[1][2]); acc[1][3]=fmaf(a.y,bq.w,acc[1][3]);
            acc[2][0]=fmaf(a.z,bq.x,acc[2][0]); acc[2][1]=fmaf(a.z,bq.y,acc[2][1]);
            acc[2][2]=fmaf(a.z,bq.z,acc[2][2]); acc[2][3]=fmaf(a.z,bq.w,acc[2][3]);
            acc[3][0]=fmaf(a.w,bq.x,acc[3][0]); acc[3][1]=fmaf(a.w,bq.y,acc[3][1]);
            acc[3][2]=fmaf(a.w,bq.z,acc[3][2]); acc[3][3]=fmaf(a.w,bq.w,acc[3][3]);
        }
        __syncthreads();
    }
    float* Tp = d_T + (size_t)b*N_*N_;
    #pragma unroll
    for (int i = 0; i < 4; ++i){
        float4 o; o.x=acc[i][0]; o.y=acc[i][1]; o.z=acc[i][2]; o.w=acc[i][3];
        *(float4*)&Tp[(size_t)(p0 + ty*4 + i)*N_ + q0 + (tx<<2)] = o;
    }
}

// ---------------------------------------------------------------------------
// numer[b,p,q] = adj>0 ? exp(T[p,q]+T[q,p]) : 0 ;  csum[b,q] += exp-or-1
// (softmax over axis p, masked entries contribute exp(0)=1 to the sum)
// ---------------------------------------------------------------------------
__global__ void k_zero(){ d_csum[blockIdx.x*256 + threadIdx.x] = 0.f; }

__global__ void k_mask(const float* __restrict__ adj){
    __shared__ float sTb[64*65];
    int tid = threadIdx.x;
    int b  = blockIdx.z;
    int p0 = blockIdx.y << 6, q0 = blockIdx.x << 6;
    const float* Tb = d_T + (size_t)b*N_*N_;
    // transposed tile T[q0+qq][p0+pp] loaded coalesced, stored [pp][qq]
    #pragma unroll
    for (int it = 0; it < 16; ++it){
        int lin = (it << 8) + tid;
        int qq = lin >> 6, pp = lin & 63;
        sTb[pp*65 + qq] = Tb[(size_t)(q0+qq)*N_ + p0 + pp];
    }
    __syncthreads();
    int c  = tid & 63;           // qq
    int r0 = (tid >> 6) << 4;    // pp start (4 threads per column x 16 rows)
    const float* adjb = adj + (size_t)b*N_*N_;
    float* nb = d_numer + (size_t)b*N_*N_;
    float part = 0.f;
    #pragma unroll 4
    for (int i = 0; i < 16; ++i){
        int pp = r0 + i;
        size_t off = (size_t)(p0+pp)*N_ + q0 + c;
        float e = Tb[off] + sTb[pp*65 + c];
        float a = adjb[off];
        float ev, nv;
        if (a > 0.f){ ev = expf(e); nv = ev; }
        else        { ev = 1.f;     nv = 0.f; }
        nb[off] = nv;
        part += ev;
    }
    atomicAdd(&d_csum[(b<<10) + q0 + c], part);
}

__global__ void k_rinv(){
    int i = blockIdx.x*256 + threadIdx.x;
    d_rsum[i] = 1.0f / d_csum[i];
}

// ---------------------------------------------------------------------------
// h'[p,:] = relu( sum_q att[p,q]*h[q,:] ), fused LSTM-style gate epilogue.
// Block: 32 rows x full 128 cols; each warp owns 4 complete rows -> warp
// shuffle reductions give the per-row scalar gates without extra passes.
// ---------------------------------------------------------------------------
__global__ void k_aggr(const float* __restrict__ x,
                       const float* __restrict__ wiu, const float* __restrict__ wix,
                       const float* __restrict__ wfu, const float* __restrict__ wfx,
                       const float* __restrict__ wou, const float* __restrict__ wox,
                       float* __restrict__ out){
    __shared__ float sW[32*32];
    __shared__ float sH[32*D_];
    int tid = threadIdx.x;
    int tx = tid & 31, ty = tid >> 5;
    int b  = blockIdx.y;
    int p0 = blockIdx.x << 5;
    const float* Wn = d_numer + (size_t)b*N_*N_;
    const float* rs = d_rsum + (b<<10);
    const float* hb = d_h + (size_t)b*N_*D_;
    float acc[4][4] = {};

    for (int q0 = 0; q0 < N_; q0 += 32){
        {
            int r = tid >> 3, c4 = (tid & 7) << 2;
            float4 v  = *(const float4*)&Wn[(size_t)(p0+r)*N_ + q0 + c4];
            float4 rv = *(const float4*)&rs[q0 + c4];
            v.x *= rv.x; v.y *= rv.y; v.z *= rv.z; v.w *= rv.w;
            *(float4*)&sW[r*32 + c4] = v;
        }
        #pragma unroll
        for (int it = 0; it < 4; ++it){
            int lin = (it << 8) + tid;
            int r = lin >> 5, c4 = (lin & 31) << 2;
            *(float4*)&sH[r*D_ + c4] = *(const float4*)&hb[(size_t)(q0+r)*D_ + c4];
        }
        __syncthreads();
        #pragma unroll
        for (int kk = 0; kk < 32; ++kk){
            float a0 = sW[(ty*4+0)*32 + kk];
            float a1 = sW[(ty*4+1)*32 + kk];
            float a2 = sW[(ty*4+2)*32 + kk];
            float a3 = sW[(ty*4+3)*32 + kk];
            float4 bq = *(float4*)&sH[kk*D_ + (tx<<2)];
            acc[0][0]=fmaf(a0,bq.x,acc[0][0]); acc[0][1]=fmaf(a0,bq.y,acc[0][1]);
            acc[0][2]=fmaf(a0,bq.z,acc[0][2]); acc[0][3]=fmaf(a0,bq.w,acc[0][3]);
            acc[1][0]=fmaf(a1,bq.x,acc[1][0]); acc[1][1]=fmaf(a1,bq.y,acc[1][1]);
            acc[1][2]=fmaf(a1,bq.z,acc[1][2]); acc[1][3]=fmaf(a1,bq.w,acc[1][3]);
            acc[2][0]=fmaf(a2,bq.x,acc[2][0]); acc[2][1]=fmaf(a2,bq.y,acc[2][1]);
            acc[2][2]=fmaf(a2,bq.z,acc[2][2]); acc[2][3]=fmaf(a2,bq.w,acc[2][3]);
            acc[3][0]=fmaf(a3,bq.x,acc[3][0]); acc[3][1]=fmaf(a3,bq.y,acc[3][1]);
            acc[3][2]=fmaf(a3,bq.z,acc[3][2]); acc[3][3]=fmaf(a3,bq.w,acc[3][3]);
        }
        __syncthreads();
    }

    // Epilogue: relu + scalar gates + output
    int col = tx << 2;
    float4 v_iu = *(const float4*)&wiu[col];
    float4 v_ix = *(const float4*)&wix[col];
    float4 v_fu = *(const float4*)&wfu[col];
    float4 v_fx = *(const float4*)&wfx[col];
    float4 v_ou = *(const float4*)&wou[col];
    float4 v_ox = *(const float4*)&wox[col];
    const float* xb = x + (size_t)b*N_*D_;
    float* ob = out + (size_t)b*N_*D_;
    #pragma unroll
    for (int i = 0; i < 4; ++i){
        int row = p0 + ty*4 + i;
        float4 xv = *(const float4*)&xb[(size_t)row*D_ + col];
        float h0 = fmaxf(acc[i][0],0.f), h1 = fmaxf(acc[i][1],0.f);
        float h2 = fmaxf(acc[i][2],0.f), h3 = fmaxf(acc[i][3],0.f);
        float si = h0*v_iu.x + h1*v_iu.y + h2*v_iu.z + h3*v_iu.w
                 + xv.x*v_ix.x + xv.y*v_ix.y + xv.z*v_ix.z + xv.w*v_ix.w;
        float sf = h0*v_fu.x + h1*v_fu.y + h2*v_fu.z + h3*v_fu.w
                 + xv.x*v_fx.x + xv.y*v_fx.y + xv.z*v_fx.z + xv.w*v_fx.w;
        float so = h0*v_ou.x + h1*v_ou.y + h2*v_ou.z + h3*v_ou.w
                 + xv.x*v_ox.x + xv.y*v_ox.y + xv.z*v_ox.z + xv.w*v_ox.w;
        #pragma unroll
        for (int off = 16; off > 0; off >>= 1){
            si += __shfl_xor_sync(0xffffffffu, si, off);
            sf += __shfl_xor_sync(0xffffffffu, sf, off);
            so += __shfl_xor_sync(0xffffffffu, so, off);
        }
        float ic = 1.f/(1.f + expf(-si));
        float fc = 1.f/(1.f + expf(-sf));
        float oc = 1.f/(1.f + expf(-so));
        float4 o;
        o.x = oc * tanhf(fmaf(ic, h0, fc*xv.x));
        o.y = oc * tanhf(fmaf(ic, h1, fc*xv.y));
        o.z = oc * tanhf(fmaf(ic, h2, fc*xv.z));
        o.w = oc * tanhf(fmaf(ic, h3, fc*xv.w));
        *(float4*)&ob[(size_t)row*D_ + col] = o;
    }
}

// ---------------------------------------------------------------------------
extern "C" void kernel_launch(void* const* d_in, const int* in_sizes, int n_in,
                              void* d_out, int out_size){
    const float* x   = (const float*)d_in[0];
    const float* adj = (const float*)d_in[1];
    const float* Ww  = (const float*)d_in[2];
    const float* Wb  = (const float*)d_in[3];
    const float* A   = (const float*)d_in[4];
    const float* wiu = (const float*)d_in[5];
    const float* wix = (const float*)d_in[6];
    const float* wfu = (const float*)d_in[7];
    const float* wfx = (const float*)d_in[8];
    const float* wou = (const float*)d_in[9];
    const float* wox = (const float*)d_in[10];
    float* out = (float*)d_out;

    k_transpose<<<64, 256>>>(Ww);
    k_h<<<(B_*N_)/32, 256>>>(x, Wb);
    k_g<<<(B_*N_)/32, 256>>>(A);
    k_score<<<dim3(N_/64, N_/64, B_), 256>>>();
    k_zero<<<(B_*N_)/256, 256>>>();
    k_mask<<<dim3(N_/64, N_/64, B_), 256>>>(adj);
    k_rinv<<<(B_*N_)/256, 256>>>();
    k_aggr<<<dim3(N_/32, B_), 256>>>(x, wiu, wix, wfu, wfx, wou, wox, out);
}

// round 3
// speedup vs baseline: 1.4693x; 1.4693x over previous
#include <cuda_runtime.h>
#include <cuda_bf16.h>
#include <cstdint>

#define B_ 16
#define N_ 1024
#define D_ 128

// ---------------------------------------------------------------------------
// Scratch (device globals — no allocation allowed)
// ---------------------------------------------------------------------------
__device__ float d_h[B_*N_*D_];                     // 8 MB fp32 h
__device__ float d_g[B_*N_*D_];                     // 8 MB fp32 gs = h@(A+A^T)
__device__ float d_WwT[D_*D_];
__device__ float d_As[D_*D_];
__device__ float d_csum[B_*N_];
__device__ float d_rsum[B_*N_];
// bf16 split operands as MMA-ready swizzled 32KB tile images (128 rows x 256B)
__device__ __nv_bfloat16 d_gsH[B_*8*16384];
__device__ __nv_bfloat16 d_gsL[B_*8*16384];
__device__ __nv_bfloat16 d_hH [B_*8*16384];
__device__ __nv_bfloat16 d_hL [B_*8*16384];
__device__ __nv_bfloat16 d_numH[(size_t)B_*N_*N_];   // 32 MB
__device__ __nv_bfloat16 d_numL[(size_t)B_*N_*N_];   // 32 MB
__device__ __nv_bfloat16 d_hsTH[B_*8*16384];
__device__ __nv_bfloat16 d_hsTL[B_*8*16384];

// ---------------------------------------------------------------------------
// helpers (all PTX here is sm_80-era: ldmatrix / mma.sync / cp.async)
// ---------------------------------------------------------------------------
__device__ __forceinline__ uint32_t smem_to_u32(const void* p){
    uint32_t a;
    asm("{ .reg .u64 t; cvta.to.shared.u64 t, %1; cvt.u32.u64 %0, t; }" : "=r"(a) : "l"(p));
    return a;
}
// XOR swizzle inside a 128-row x 256-byte tile: 16B chunk index ^= (row & 7)
__device__ __forceinline__ uint32_t swz(int row, int kbyte){
    return (uint32_t)(row*256) + (uint32_t)(((((kbyte >> 4) ^ (row & 7)) << 4)) | (kbyte & 15));
}
__device__ __forceinline__ void ldm16x16(uint32_t base, int row0, int k0, uint32_t r[4]){
    int lane = threadIdx.x & 31;
    uint32_t addr = base + swz(row0 + (lane & 15), k0*2 + ((lane >> 4) << 4));
    asm volatile("ldmatrix.sync.aligned.m8n8.x4.shared.b16 {%0,%1,%2,%3}, [%4];"
        : "=r"(r[0]), "=r"(r[1]), "=r"(r[2]), "=r"(r[3]) : "r"(addr));
}
__device__ __forceinline__ void mma16816(float* d, const uint32_t* a, uint32_t b0, uint32_t b1){
    asm volatile("mma.sync.aligned.m16n8k16.row.col.f32.bf16.bf16.f32 "
        "{%0,%1,%2,%3}, {%4,%5,%6,%7}, {%8,%9}, {%0,%1,%2,%3};"
        : "+f"(d[0]), "+f"(d[1]), "+f"(d[2]), "+f"(d[3])
        : "r"(a[0]), "r"(a[1]), "r"(a[2]), "r"(a[3]), "r"(b0), "r"(b1));
}
__device__ __forceinline__ void cpy_tile(uint32_t sdst, const char* g, int tid){
    for (int i = tid; i < 2048; i += 256){
        asm volatile("cp.async.cg.shared.global [%0], [%1], 16;"
            :: "r"(sdst + (uint32_t)i*16), "l"(g + (size_t)i*16));
    }
}
#define CP_COMMIT_WAIT() do { \
    asm volatile("cp.async.commit_group;" ::: "memory"); \
    asm volatile("cp.async.wait_group 0;" ::: "memory"); } while(0)

__device__ __forceinline__ void split8(const float* v, uint4& uh, uint4& ul){
    uint32_t h[4], l[4];
    #pragma unroll
    for (int i = 0; i < 4; ++i){
        float a = v[2*i], b = v[2*i+1];
        __nv_bfloat16 ah = __float2bfloat16(a), bh = __float2bfloat16(b);
        __nv_bfloat16 al = __float2bfloat16(a - __bfloat162float(ah));
        __nv_bfloat16 bl = __float2bfloat16(b - __bfloat162float(bh));
        h[i] = (uint32_t)__bfloat16_as_ushort(ah) | ((uint32_t)__bfloat16_as_ushort(bh) << 16);
        l[i] = (uint32_t)__bfloat16_as_ushort(al) | ((uint32_t)__bfloat16_as_ushort(bl) << 16);
    }
    uh = make_uint4(h[0],h[1],h[2],h[3]); ul = make_uint4(l[0],l[1],l[2],l[3]);
}

// ---------------------------------------------------------------------------
// prep kernels
// ---------------------------------------------------------------------------
__global__ void k_prep(const float* __restrict__ Ww, const float* __restrict__ A){
    int idx = blockIdx.x*256 + threadIdx.x;
    int r = idx >> 7, c = idx & 127;
    d_WwT[c*D_ + r] = Ww[r*D_ + c];
    d_As[r*D_ + c]  = A[r*D_ + c] + A[c*D_ + r];
}

// fp32 NN tile (validated round 1)
__device__ __forceinline__ void nn_tile(const float* __restrict__ Arows,
                                        const float* __restrict__ Brows,
                                        const float* __restrict__ bias,
                                        float* __restrict__ out){
    __shared__ float sA[32*32];
    __shared__ float sB[32*D_];
    int tid = threadIdx.x, tx = tid & 31, ty = tid >> 5;
    int rowBase = blockIdx.x << 5;
    float acc[4][4] = {};
    for (int k0 = 0; k0 < D_; k0 += 32){
        { int r = tid >> 3, c4 = (tid & 7) << 2;
          *(float4*)&sA[r*32 + c4] = *(const float4*)&Arows[(size_t)(rowBase + r)*D_ + k0 + c4]; }
        #pragma unroll
        for (int it = 0; it < 4; ++it){
            int lin = (it << 8) + tid, r = lin >> 5, c4 = (lin & 31) << 2;
            *(float4*)&sB[r*D_ + c4] = *(const float4*)&Brows[(size_t)(k0 + r)*D_ + c4];
        }
        __syncthreads();
        #pragma unroll
        for (int kk = 0; kk < 32; ++kk){
            float a0 = sA[(ty*4+0)*32+kk], a1 = sA[(ty*4+1)*32+kk];
            float a2 = sA[(ty*4+2)*32+kk], a3 = sA[(ty*4+3)*32+kk];
            float4 b = *(float4*)&sB[kk*D_ + (tx<<2)];
            acc[0][0]=fmaf(a0,b.x,acc[0][0]); acc[0][1]=fmaf(a0,b.y,acc[0][1]);
            acc[0][2]=fmaf(a0,b.z,acc[0][2]); acc[0][3]=fmaf(a0,b.w,acc[0][3]);
            acc[1][0]=fmaf(a1,b.x,acc[1][0]); acc[1][1]=fmaf(a1,b.y,acc[1][1]);
            acc[1][2]=fmaf(a1,b.z,acc[1][2]); acc[1][3]=fmaf(a1,b.w,acc[1][3]);
            acc[2][0]=fmaf(a2,b.x,acc[2][0]); acc[2][1]=fmaf(a2,b.y,acc[2][1]);
            acc[2][2]=fmaf(a2,b.z,acc[2][2]); acc[2][3]=fmaf(a2,b.w,acc[2][3]);
            acc[3][0]=fmaf(a3,b.x,acc[3][0]); acc[3][1]=fmaf(a3,b.y,acc[3][1]);
            acc[3][2]=fmaf(a3,b.z,acc[3][2]); acc[3][3]=fmaf(a3,b.w,acc[3][3]);
        }
        __syncthreads();
    }
    float4 bv = make_float4(0.f,0.f,0.f,0.f);
    if (bias) bv = *(const float4*)&bias[tx<<2];
    #pragma unroll
    for (int i = 0; i < 4; ++i){
        float4 o; o.x=acc[i][0]+bv.x; o.y=acc[i][1]+bv.y; o.z=acc[i][2]+bv.z; o.w=acc[i][3]+bv.w;
        *(float4*)&out[(size_t)(rowBase + ty*4 + i)*D_ + (tx<<2)] = o;
    }
}
__global__ void k_h(const float* __restrict__ x, const float* __restrict__ Wb){
    nn_tile(x, d_WwT, Wb, d_h);
}
__global__ void k_g(){ nn_tile(d_h, d_As, nullptr, d_g); }

// split gs,h into hi/lo bf16 swizzled tiles (row = node, k = feature)
__global__ void k_split(){
    int ct = blockIdx.x, b = blockIdx.y, tid = threadIdx.x;
    size_t tileB = (size_t)(b*8 + ct)*32768;
    int p0 = ct*128;
    for (int pass = 0; pass < 2; ++pass){
        const float* src = pass ? d_h : d_g;
        char* dh = (char*)(pass ? d_hH : d_gsH) + tileB;
        char* dl = (char*)(pass ? d_hL : d_gsL) + tileB;
        for (int g = tid; g < 2048; g += 256){
            int row = g >> 4, col = (g & 15) << 3;
            float v[8];
            const float* sp = &src[((size_t)(b*N_) + p0 + row)*D_ + col];
            *(float4*)v = *(const float4*)sp; *(float4*)(v+4) = *(const float4*)(sp+4);
            uint4 uh, ul; split8(v, uh, ul);
            uint32_t off = swz(row, col*2);
            *(uint4*)(dh + off) = uh; *(uint4*)(dl + off) = ul;
        }
    }
}

__global__ void k_zero(){ d_csum[blockIdx.x*256 + threadIdx.x] = 0.f; }
__global__ void k_rinv(){ int i = blockIdx.x*256 + threadIdx.x; d_rsum[i] = 1.0f / d_csum[i]; }

// hsT[d][q] = h[q][d] * rsum[q]  -> swizzled B-tile images (row = d, k = q)
__global__ void k_hsT(){
    extern __shared__ float sT[];   // 128*129
    int qc = blockIdx.x, b = blockIdx.y, tid = threadIdx.x;
    int q0 = qc*128;
    for (int g = tid; g < 2048; g += 256){
        int q = g >> 4, col = (g & 15) << 3;
        float r = d_rsum[b*N_ + q0 + q];
        const float* sp = &d_h[((size_t)(b*N_) + q0 + q)*D_ + col];
        #pragma unroll
        for (int i = 0; i < 8; ++i) sT[(col + i)*129 + q] = sp[i]*r;
    }
    __syncthreads();
    size_t tileB = (size_t)(b*8 + qc)*32768;
    for (int g = tid; g < 2048; g += 256){
        int dd = g >> 4, q8 = (g & 15) << 3;
        float v[8];
        #pragma unroll
        for (int i = 0; i < 8; ++i) v[i] = sT[dd*129 + q8 + i];
        uint4 uh, ul; split8(v, uh, ul);
        uint32_t off = swz(dd, q8*2);
        *(uint4*)((char*)d_hsTH + tileB + off) = uh;
        *(uint4*)((char*)d_hsTL + tileB + off) = ul;
    }
}

// ---------------------------------------------------------------------------
// smem layout (shared by kB / kC): operand tiles while MMAing, then reuse
// ---------------------------------------------------------------------------
#define S_AH 0
#define S_AL 32768
#define S_BH 65536
#define S_BL 98304
#define S_SH 66560
#define S_SL 99328
#define S_SCOL 132096
#define SMEM_BYTES 132608

// 3-term bf16 split MMA over one 128x128xK=128 tile set (warp grid 2m x 4n)
__device__ __forceinline__ void mma_tileset(uint32_t sb, int m0, int n0, float acc[4][4][4]){
    #pragma unroll
    for (int ks = 0; ks < 8; ++ks){
        int k0 = ks*16;
        uint32_t aH[4][4], aL[4][4], bH[2][4], bL[2][4];
        #pragma unroll
        for (int mt = 0; mt < 4; ++mt){
            ldm16x16(sb + S_AH, m0 + mt*16, k0, aH[mt]);
            ldm16x16(sb + S_AL, m0 + mt*16, k0, aL[mt]);
        }
        #pragma unroll
        for (int np = 0; np < 2; ++np){
            ldm16x16(sb + S_BH, n0 + np*16, k0, bH[np]);
            ldm16x16(sb + S_BL, n0 + np*16, k0, bL[np]);
        }
        #pragma unroll
        for (int mt = 0; mt < 4; ++mt)
        #pragma unroll
        for (int np = 0; np < 2; ++np)
        #pragma unroll
        for (int hf = 0; hf < 2; ++hf){
            float* d = acc[mt][np*2 + hf];
            mma16816(d, aH[mt], bH[np][hf], bH[np][2 + hf]);
            mma16816(d, aH[mt], bL[np][hf], bL[np][2 + hf]);
            mma16816(d, aL[mt], bH[np][hf], bH[np][2 + hf]);
        }
    }
}

// ---------------------------------------------------------------------------
// Score kernel: e = gs @ h^T, fused mask/exp/colsum, numer written as
// pre-swizzled hi/lo tile images (the aggregation kernel's A operand).
// ---------------------------------------------------------------------------
__global__ void __launch_bounds__(256, 1) kB(const float* __restrict__ adj){
    extern __shared__ char smem[];
    uint32_t sb = smem_to_u32(smem);
    int tid = threadIdx.x, lane = tid & 31, wid = tid >> 5;
    int qt = blockIdx.x, pt = blockIdx.y, b = blockIdx.z;
    int m0 = (wid >> 2)*64, n0 = (wid & 3)*32;

    size_t tgs = (size_t)(b*8 + pt)*32768, th = (size_t)(b*8 + qt)*32768;
    cpy_tile(sb + S_AH, (const char*)d_gsH + tgs, tid);
    cpy_tile(sb + S_AL, (const char*)d_gsL + tgs, tid);
    cpy_tile(sb + S_BH, (const char*)d_hH  + th,  tid);
    cpy_tile(sb + S_BL, (const char*)d_hL  + th,  tid);
    CP_COMMIT_WAIT();
    __syncthreads();

    float acc[4][4][4] = {};
    mma_tileset(sb, m0, n0, acc);
    __syncthreads();

    // reuse operand smem: adj tile [128][129] + scol
    float* sAdj = (float*)smem;
    const float* adjb = adj + (size_t)b*N_*N_ + (size_t)(pt*128)*N_ + qt*128;
    for (int g = tid; g < 4096; g += 256){
        int row = g >> 5, c4 = (g & 31) << 2;
        float4 v = *(const float4*)&adjb[(size_t)row*N_ + c4];
        float* p = &sAdj[row*129 + c4];
        p[0]=v.x; p[1]=v.y; p[2]=v.z; p[3]=v.w;
    }
    float* scol = (float*)(smem + S_SCOL);
    if (tid < 128) scol[tid] = 0.f;
    __syncthreads();

    char* stH = smem + S_SH; char* stL = smem + S_SL;
    float cs[8] = {};
    #pragma unroll
    for (int mt = 0; mt < 4; ++mt){
        int r1 = m0 + mt*16 + (lane >> 2);
        #pragma unroll
        for (int nt = 0; nt < 4; ++nt){
            int c0 = n0 + nt*8 + ((lane & 3) << 1);
            const float* d = acc[mt][nt];
            #pragma unroll
            for (int hf = 0; hf < 2; ++hf){
                int r = r1 + hf*8;
                float e0 = d[hf*2 + 0], e1 = d[hf*2 + 1];
                float a0 = sAdj[r*129 + c0], a1 = sAdj[r*129 + c0 + 1];
                float ev0 = (a0 > 0.f) ? expf(e0) : 1.f;
                float ev1 = (a1 > 0.f) ? expf(e1) : 1.f;
                float nv0 = (a0 > 0.f) ? ev0 : 0.f;
                float nv1 = (a1 > 0.f) ? ev1 : 0.f;
                cs[nt*2 + 0] += ev0; cs[nt*2 + 1] += ev1;
                __nv_bfloat16 h0 = __float2bfloat16(nv0);
                __nv_bfloat16 h1 = __float2bfloat16(nv1);
                __nv_bfloat16 l0 = __float2bfloat16(nv0 - __bfloat162float(h0));
                __nv_bfloat16 l1 = __float2bfloat16(nv1 - __bfloat162float(h1));
                uint32_t off = swz(r, c0*2);
                *(uint32_t*)(stH + off) =
                    (uint32_t)__bfloat16_as_ushort(h0) | ((uint32_t)__bfloat16_as_ushort(h1) << 16);
                *(uint32_t*)(stL + off) =
                    (uint32_t)__bfloat16_as_ushort(l0) | ((uint32_t)__bfloat16_as_ushort(l1) << 16);
            }
        }
    }
    #pragma unroll
    for (int m = 4; m < 32; m <<= 1){
        #pragma unroll
        for (int i = 0; i < 8; ++i) cs[i] += __shfl_xor_sync(0xffffffffu, cs[i], m);
    }
    if (lane < 4){
        #pragma unroll
        for (int nt = 0; nt < 4; ++nt){
            atomicAdd(&scol[n0 + nt*8 + 2*lane],     cs[nt*2]);
            atomicAdd(&scol[n0 + nt*8 + 2*lane + 1], cs[nt*2 + 1]);
        }
    }
    __syncthreads();
    if (tid < 128) atomicAdd(&d_csum[b*N_ + qt*128 + tid], scol[tid]);

    size_t tnum = (size_t)(b*64 + pt*8 + qt)*32768;
    { uint4* gd = (uint4*)((char*)d_numH + tnum); const uint4* ss = (const uint4*)stH;
      for (int i = tid; i < 2048; i += 256) gd[i] = ss[i]; }
    { uint4* gd = (uint4*)((char*)d_numL + tnum); const uint4* ss = (const uint4*)stL;
      for (int i = tid; i < 2048; i += 256) gd[i] = ss[i]; }
}

// ---------------------------------------------------------------------------
// Aggregation: h' = numer @ hsT^T over 8 K-chunks, fused relu + gates + tanh
// ---------------------------------------------------------------------------
__global__ void __launch_bounds__(256, 1) kC(const float* __restrict__ x,
        const float* __restrict__ wiu, const float* __restrict__ wix,
        const float* __restrict__ wfu, const float* __restrict__ wfx,
        const float* __restrict__ wou, const float* __restrict__ wox,
        float* __restrict__ out){
    extern __shared__ char smem[];
    uint32_t sb = smem_to_u32(smem);
    int tid = threadIdx.x, lane = tid & 31, wid = tid >> 5;
    int pt = blockIdx.x, b = blockIdx.y;
    int m0 = (wid >> 2)*64, n0 = (wid & 3)*32, wn = wid & 3;

    float acc[4][4][4] = {};
    for (int qc = 0; qc < 8; ++qc){
        size_t tn = (size_t)(b*64 + pt*8 + qc)*32768;
        size_t tb = (size_t)(b*8 + qc)*32768;
        cpy_tile(sb + S_AH, (const char*)d_numH + tn, tid);
        cpy_tile(sb + S_AL, (const char*)d_numL + tn, tid);
        cpy_tile(sb + S_BH, (const char*)d_hsTH + tb, tid);
        cpy_tile(sb + S_BL, (const char*)d_hsTL + tb, tid);
        CP_COMMIT_WAIT();
        __syncthreads();
        mma_tileset(sb, m0, n0, acc);
        __syncthreads();
    }

    // epilogue staging (reuse operand smem)
    float* sx    = (float*)smem;                 // [128][129]
    float* sw    = (float*)(smem + 66560);       // [6][128]
    float* sPart = (float*)(smem + 69632);       // [4 wn][3][128]
    float* sGate = (float*)(smem + 75776);       // [3][128]
    const float* xb = x + ((size_t)b*N_ + pt*128)*D_;
    for (int g = tid; g < 4096; g += 256){
        int row = g >> 5, c4 = (g & 31) << 2;
        float4 v = *(const float4*)&xb[(size_t)row*D_ + c4];
        float* p = &sx[row*129 + c4];
        p[0]=v.x; p[1]=v.y; p[2]=v.z; p[3]=v.w;
    }
    if (tid < 128){
        sw[tid]       = wiu[tid]; sw[128 + tid] = wfu[tid]; sw[256 + tid] = wou[tid];
        sw[384 + tid] = wix[tid]; sw[512 + tid] = wfx[tid]; sw[640 + tid] = wox[tid];
    }
    __syncthreads();

    // per-thread gate partials (relu'd h' dotted with wu weights)
    float pi[8] = {}, pf[8] = {}, po[8] = {};
    #pragma unroll
    for (int mt = 0; mt < 4; ++mt){
        #pragma unroll
        for (int nt = 0; nt < 4; ++nt){
            int c0 = n0 + nt*8 + ((lane & 3) << 1);
            float wi0 = sw[c0], wi1 = sw[c0+1];
            float wf0 = sw[128+c0], wf1 = sw[129+c0];
            float wo0 = sw[256+c0], wo1 = sw[257+c0];
            const float* d = acc[mt][nt];
            #pragma unroll
            for (int hf = 0; hf < 2; ++hf){
                float h0 = fmaxf(d[hf*2], 0.f), h1 = fmaxf(d[hf*2+1], 0.f);
                pi[mt*2+hf] += h0*wi0 + h1*wi1;
                pf[mt*2+hf] += h0*wf0 + h1*wf1;
                po[mt*2+hf] += h0*wo0 + h1*wo1;
            }
        }
    }
    #pragma unroll
    for (int m = 1; m < 4; m <<= 1){
        #pragma unroll
        for (int i = 0; i < 8; ++i){
            pi[i] += __shfl_xor_sync(0xffffffffu, pi[i], m);
            pf[i] += __shfl_xor_sync(0xffffffffu, pf[i], m);
            po[i] += __shfl_xor_sync(0xffffffffu, po[i], m);
        }
    }
    if ((lane & 3) == 0){
        #pragma unroll
        for (int mt = 0; mt < 4; ++mt)
        #pragma unroll
        for (int hf = 0; hf < 2; ++hf){
            int rl = m0 + mt*16 + (lane >> 2) + hf*8;
            sPart[(wn*3 + 0)*128 + rl] = pi[mt*2+hf];
            sPart[(wn*3 + 1)*128 + rl] = pf[mt*2+hf];
            sPart[(wn*3 + 2)*128 + rl] = po[mt*2+hf];
        }
    }
    __syncthreads();
    if (tid < 128){
        int r = tid;
        float si = 0.f, sf = 0.f, so = 0.f;
        #pragma unroll
        for (int w = 0; w < 4; ++w){
            si += sPart[(w*3 + 0)*128 + r];
            sf += sPart[(w*3 + 1)*128 + r];
            so += sPart[(w*3 + 2)*128 + r];
        }
        const float* srow = &sx[r*129];
        #pragma unroll 8
        for (int c = 0; c < 128; ++c){
            float xv = srow[c];
            si = fmaf(xv, sw[384 + c], si);
            sf = fmaf(xv, sw[512 + c], sf);
            so = fmaf(xv, sw[640 + c], so);
        }
        sGate[r]         = 1.f/(1.f + expf(-si));
        sGate[128 + r]   = 1.f/(1.f + expf(-sf));
        sGate[256 + r]   = 1.f/(1.f + expf(-so));
    }
    __syncthreads();

    float* outb = out + ((size_t)b*N_ + pt*128)*D_;
    #pragma unroll
    for (int mt = 0; mt < 4; ++mt){
        #pragma unroll
        for (int nt = 0; nt < 4; ++nt){
            int c0 = n0 + nt*8 + ((lane & 3) << 1);
            const float* d = acc[mt][nt];
            #pragma unroll
            for (int hf = 0; hf < 2; ++hf){
                int rl = m0 + mt*16 + (lane >> 2) + hf*8;
                float ic = sGate[rl], fc = sGate[128 + rl], oc = sGate[256 + rl];
                float x0 = sx[rl*129 + c0], x1 = sx[rl*129 + c0 + 1];
                float h0 = fmaxf(d[hf*2], 0.f), h1 = fmaxf(d[hf*2+1], 0.f);
                float2 o;
                o.x = oc * tanhf(fmaf(ic, h0, fc*x0));
                o.y = oc * tanhf(fmaf(ic, h1, fc*x1));
                *(float2*)&outb[(size_t)rl*D_ + c0] = o;
            }
        }
    }
}

// ---------------------------------------------------------------------------
extern "C" void kernel_launch(void* const* d_in, const int* in_sizes, int n_in,
                              void* d_out, int out_size){
    const float* x   = (const float*)d_in[0];
    const float* adj = (const float*)d_in[1];
    const float* Ww  = (const float*)d_in[2];
    const float* Wb  = (const float*)d_in[3];
    const float* A   = (const float*)d_in[4];
    const float* wiu = (const float*)d_in[5];
    const float* wix = (const float*)d_in[6];
    const float* wfu = (const float*)d_in[7];
    const float* wfx = (const float*)d_in[8];
    const float* wou = (const float*)d_in[9];
    const float* wox = (const float*)d_in[10];
    float* out = (float*)d_out;

    cudaFuncSetAttribute(kB, cudaFuncAttributeMaxDynamicSharedMemorySize, SMEM_BYTES);
    cudaFuncSetAttribute(kC, cudaFuncAttributeMaxDynamicSharedMemorySize, SMEM_BYTES);
    cudaFuncSetAttribute(k_hsT, cudaFuncAttributeMaxDynamicSharedMemorySize, 128*129*4);

    k_prep<<<64, 256>>>(Ww, A);
    k_h<<<(B_*N_)/32, 256>>>(x, Wb);
    k_g<<<(B_*N_)/32, 256>>>();
    k_split<<<dim3(8, B_), 256>>>();
    k_zero<<<(B_*N_)/256, 256>>>();
    kB<<<dim3(8, 8, B_), 256, SMEM_BYTES>>>(adj);
    k_rinv<<<(B_*N_)/256, 256>>>();
    k_hsT<<<dim3(8, B_), 256, 128*129*4>>>();
    kC<<<dim3(8, B_), 256, SMEM_BYTES>>>(x, wiu, wix, wfu, wfx, wou, wox, out);
}